// round 7
// baseline (speedup 1.0000x reference)
#include <cuda_runtime.h>
#include <math.h>
#include <stddef.h>
#include <stdint.h>

#define B_ 256
#define W_ 512
#define F_ 512
#define N_ 512
#define WT 16                 // words per tile (== #warps in k_attn)
#define NT (W_ / WT)          // 32 tiles
#define NBUF 3                // pipeline depth

// Scratch (device globals — no allocation allowed)
__device__ float g_t [B_*F_];   // t  = sum_w w[w]*x[b,w,:]
__device__ float g_q [B_*N_];   // Q  = t @ wq
__device__ float g_qk[B_*F_];   // qk = (Q @ wk^T) * rsqrt(N)
__device__ float g_y [B_*F_];   // y  = sum_w softmax_w * x[b,w,:]

// ---------------------------------------------------------------------------
// cp.async helpers
// ---------------------------------------------------------------------------
__device__ __forceinline__ void cp_async16(void* dst_smem, const void* src_gmem) {
    uint32_t d = (uint32_t)__cvta_generic_to_shared(dst_smem);
    asm volatile("cp.async.cg.shared.global [%0], [%1], 16;\n" :: "r"(d), "l"(src_gmem));
}
__device__ __forceinline__ void cp_commit() {
    asm volatile("cp.async.commit_group;\n");
}
template <int Nw>
__device__ __forceinline__ void cp_wait() {
    asm volatile("cp.async.wait_group %0;\n" :: "n"(Nw));
}

// Issue one WT x F_ tile (2048 float4) into smem buffer; 4 cp.async per thread.
__device__ __forceinline__ void issue_tile(float* dst, const float4* xb4,
                                           int t0, int tid) {
    #pragma unroll
    for (int j = 0; j < 4; j++) {
        int e = tid + j * 512;               // 0..2047
        int w = e >> 7, f4 = e & 127;
        cp_async16(&dst[w * F_ + f4 * 4], &xb4[(size_t)(t0 + w) * 128 + f4]);
    }
    cp_commit();
}

// ---------------------------------------------------------------------------
// Pass A: t[b][f] = sum_w w[w] * x[b][w][f]
// One CTA per batch, 512 threads, 2 CTAs/SM, 3-stage cp.async pipeline.
// Dynamic smem: ws[512] | buf[NBUF][WT*512]   (100352 B)
// ---------------------------------------------------------------------------
__global__ __launch_bounds__(512, 2) void k_t(const float* __restrict__ x,
                                              const float* __restrict__ wvec) {
    extern __shared__ float sm[];
    float* ws = sm;                          // 512
    float* bufs[NBUF];
    #pragma unroll
    for (int i = 0; i < NBUF; i++) bufs[i] = sm + F_ + i * WT * F_;

    const int b = blockIdx.x, tid = threadIdx.x;
    const float4* xb4 = (const float4*)(x + (size_t)b * W_ * F_);

    ws[tid] = wvec[tid];
    issue_tile(bufs[0], xb4, 0, tid);
    issue_tile(bufs[1], xb4, WT, tid);

    float acc = 0.f;
    for (int t = 0; t < NT; t++) {
        if (t < NT - 1) cp_wait<1>(); else cp_wait<0>();
        __syncthreads();                     // tile t ready; all done reading t-1
        if (t + 2 < NT)
            issue_tile(bufs[(t + 2) % NBUF], xb4, (t + 2) * WT, tid);

        const float* xt = bufs[t % NBUF];
        const float* wst = ws + t * WT;
        #pragma unroll
        for (int w = 0; w < WT; w++)
            acc += wst[w] * xt[w * F_ + tid];
    }
    g_t[b * F_ + tid] = acc;
}

// ---------------------------------------------------------------------------
// 32x32 tiled SGEMM, BK=32, 256 threads, 2x2 micro with LDS.64.
// C = A[M,Kk] @ (TRANS_B ? Bm[Nn,Kk]^T : Bm[Kk,Nn]) * scale
// ---------------------------------------------------------------------------
template <int TRANS_B>
__global__ __launch_bounds__(256) void gemm32(const float* __restrict__ A,
                                              const float* __restrict__ Bm,
                                              float* __restrict__ C,
                                              int M, int Nn, int Kk, float scale) {
    __shared__ float As[32][36];
    __shared__ float Bs[32][36];
    const int tid = threadIdx.x;
    const int tx = tid & 15, ty = tid >> 4;
    const int m0 = blockIdx.y * 32, n0 = blockIdx.x * 32;
    float c00 = 0.f, c01 = 0.f, c10 = 0.f, c11 = 0.f;

    const int lm = tid >> 3, lk4 = tid & 7;

    for (int k0 = 0; k0 < Kk; k0 += 32) {
        {
            float4 v = *(const float4*)&A[(size_t)(m0 + lm) * Kk + k0 + lk4 * 4];
            As[lk4 * 4 + 0][lm] = v.x;
            As[lk4 * 4 + 1][lm] = v.y;
            As[lk4 * 4 + 2][lm] = v.z;
            As[lk4 * 4 + 3][lm] = v.w;
        }
        if (TRANS_B) {
            float4 v = *(const float4*)&Bm[(size_t)(n0 + lm) * Kk + k0 + lk4 * 4];
            Bs[lk4 * 4 + 0][lm] = v.x;
            Bs[lk4 * 4 + 1][lm] = v.y;
            Bs[lk4 * 4 + 2][lm] = v.z;
            Bs[lk4 * 4 + 3][lm] = v.w;
        } else {
            float4 v = *(const float4*)&Bm[(size_t)(k0 + lm) * Nn + n0 + lk4 * 4];
            Bs[lm][lk4 * 4 + 0] = v.x;
            Bs[lm][lk4 * 4 + 1] = v.y;
            Bs[lm][lk4 * 4 + 2] = v.z;
            Bs[lm][lk4 * 4 + 3] = v.w;
        }
        __syncthreads();
        #pragma unroll
        for (int k = 0; k < 32; k++) {
            const float2 a = *(const float2*)&As[k][ty * 2];
            const float2 b = *(const float2*)&Bs[k][tx * 2];
            c00 += a.x * b.x; c01 += a.x * b.y;
            c10 += a.y * b.x; c11 += a.y * b.y;
        }
        __syncthreads();
    }
    float* Cp = C + (size_t)(m0 + ty * 2) * Nn + n0 + tx * 2;
    Cp[0] = c00 * scale;  Cp[1] = c01 * scale;
    Cp[Nn] = c10 * scale; Cp[Nn + 1] = c11 * scale;
}

// ---------------------------------------------------------------------------
// Pass B: scores + online softmax + weighted accumulate.
// One CTA per batch, 512 threads, 2 CTAs/SM, 3-stage cp.async pipeline.
// Dynamic smem: qks[512] | buf[NBUF][WT*512]   (100352 B)
// ---------------------------------------------------------------------------
__global__ __launch_bounds__(512, 2) void k_attn(const float* __restrict__ x) {
    extern __shared__ float sm[];
    float* qks = sm;
    float* bufs[NBUF];
    #pragma unroll
    for (int i = 0; i < NBUF; i++) bufs[i] = sm + F_ + i * WT * F_;
    __shared__ float sc[WT];
    __shared__ float ps[WT];

    const int b = blockIdx.x, tid = threadIdx.x;
    const int wi = tid >> 5, lane = tid & 31;
    const float4* xb4 = (const float4*)(x + (size_t)b * W_ * F_);

    qks[tid] = g_qk[b * F_ + tid];
    issue_tile(bufs[0], xb4, 0, tid);
    issue_tile(bufs[1], xb4, WT, tid);
    __syncthreads();                         // qks visible

    // This thread's slice of qk for the dot phase (float4 layout)
    float4 qkr4[4];
    const float4* qks4 = (const float4*)qks;
    #pragma unroll
    for (int j = 0; j < 4; j++) qkr4[j] = qks4[lane + 32 * j];

    float m = -1e30f, s = 0.f, y = 0.f;

    for (int t = 0; t < NT; t++) {
        if (t < NT - 1) cp_wait<1>(); else cp_wait<0>();
        __syncthreads();                     // tile t ready; all done reading t-1
        if (t + 2 < NT)
            issue_tile(bufs[(t + 2) % NBUF], xb4, (t + 2) * WT, tid);

        const float* xt = bufs[t % NBUF];

        // Each warp: one word's dot (LDS.128), qk already carries rsqrt(N)
        float d = 0.f;
        const float4* xw4 = (const float4*)&xt[wi * F_];
        #pragma unroll
        for (int j = 0; j < 4; j++) {
            const float4 v = xw4[lane + 32 * j];
            d += v.x * qkr4[j].x + v.y * qkr4[j].y
               + v.z * qkr4[j].z + v.w * qkr4[j].w;
        }
        #pragma unroll
        for (int o = 16; o > 0; o >>= 1) d += __shfl_xor_sync(0xffffffffu, d, o);
        if (lane == 0) sc[wi] = d;
        __syncthreads();                     // sc ready

        float mn = m;
        #pragma unroll
        for (int w = 0; w < WT; w++) mn = fmaxf(mn, sc[w]);
        const float corr = __expf(m - mn);
        if (tid < WT) ps[tid] = __expf(sc[tid] - mn);
        m = mn;
        __syncthreads();                     // ps ready

        float pr[WT];
        #pragma unroll
        for (int w = 0; w < WT; w++) pr[w] = ps[w];
        float psum = 0.f;
        #pragma unroll
        for (int w = 0; w < WT; w++) psum += pr[w];
        s = s * corr + psum;
        y *= corr;
        #pragma unroll
        for (int w = 0; w < WT; w++) y += pr[w] * xt[w * F_ + tid];
        // no trailing barrier: next iteration's first __syncthreads() fences
        // the buffer that gets re-issued, and sc/ps writes are barrier-guarded.
    }
    g_y[b * F_ + tid] = y / s;
}

// ---------------------------------------------------------------------------
extern "C" void kernel_launch(void* const* d_in, const int* in_sizes, int n_in,
                              void* d_out, int out_size) {
    const float* x    = (const float*)d_in[0];
    const float* wk   = (const float*)d_in[1];
    const float* wq   = (const float*)d_in[2];
    const float* wv   = (const float*)d_in[3];
    const float* wvec = (const float*)d_in[4];
    float* out = (float*)d_out;

    float *pt, *pq, *pqk, *py;
    cudaGetSymbolAddress((void**)&pt,  g_t);
    cudaGetSymbolAddress((void**)&pq,  g_q);
    cudaGetSymbolAddress((void**)&pqk, g_qk);
    cudaGetSymbolAddress((void**)&py,  g_y);

    const int pipe_smem = (F_ + NBUF * WT * F_) * sizeof(float);   // 100352
    cudaFuncSetAttribute(k_t,    cudaFuncAttributeMaxDynamicSharedMemorySize, pipe_smem);
    cudaFuncSetAttribute(k_attn, cudaFuncAttributeMaxDynamicSharedMemorySize, pipe_smem);

    const float rsqrtN = 0.04419417382415922f;  // 1/sqrt(512)

    // Pass A over x: t
    k_t<<<B_, 512, pipe_smem>>>(x, wvec);
    // Q = t @ wq                 (256x512x512)
    gemm32<0><<<dim3(N_ / 32, B_ / 32), 256>>>(pt, wq, pq, B_, N_, F_, 1.f);
    // qk = (Q @ wk^T) * rsqrtN   (256x512x512)
    gemm32<1><<<dim3(F_ / 32, B_ / 32), 256>>>(pq, wk, pqk, B_, F_, N_, rsqrtN);
    // Pass B over x: attention
    k_attn<<<B_, 512, pipe_smem>>>(x);
    // out = y @ wv               (256x512x512)
    gemm32<0><<<dim3(N_ / 32, B_ / 32), 256>>>(py, wv, out, B_, N_, F_, 1.f);
}

// round 8
// speedup vs baseline: 1.1468x; 1.1468x over previous
#include <cuda_runtime.h>
#include <math.h>
#include <stddef.h>
#include <stdint.h>

#define B_ 256
#define W_ 512
#define F_ 512
#define N_ 512
#define WT 16                 // words per tile (== #warps)
#define NT (W_ / WT)          // 32 tiles

// Scratch (device globals — no allocation allowed)
__device__ float g_t [B_*F_];   // t  = sum_w w[w]*x[b,w,:]
__device__ float g_q [B_*N_];   // Q  = t @ wq
__device__ float g_qk[B_*F_];   // qk = (Q @ wk^T) * rsqrt(N)
__device__ float g_y [B_*F_];   // y  = sum_w softmax_w * x[b,w,:]

// ---------------------------------------------------------------------------
// cp.async helpers
// ---------------------------------------------------------------------------
__device__ __forceinline__ void cp_async16(void* dst_smem, const void* src_gmem) {
    uint32_t d = (uint32_t)__cvta_generic_to_shared(dst_smem);
    asm volatile("cp.async.cg.shared.global [%0], [%1], 16;\n" :: "r"(d), "l"(src_gmem));
}
__device__ __forceinline__ void cp_commit() {
    asm volatile("cp.async.commit_group;\n");
}
template <int Nw>
__device__ __forceinline__ void cp_wait() {
    asm volatile("cp.async.wait_group %0;\n" :: "n"(Nw));
}

// Issue one WT x F_ tile (2048 float4) into smem buffer; 4 cp.async/thread.
__device__ __forceinline__ void issue_tile(float* dst, const float4* xb4,
                                           int t0, int tid) {
    #pragma unroll
    for (int j = 0; j < 4; j++) {
        int e = tid + j * 512;               // 0..2047
        int w = e >> 7, f4 = e & 127;
        cp_async16(&dst[w * F_ + f4 * 4], &xb4[(size_t)(t0 + w) * 128 + f4]);
    }
    cp_commit();
}

// ---------------------------------------------------------------------------
// Pass A: t[b][f] = sum_w w[w] * x[b][w][f]
// One CTA per batch, 512 threads, 2 CTAs/SM, 2-buffer cp.async pipeline
// with the R6-proven schedule: issue next -> wait<1> -> compute current.
// Tiles processed DESCENDING so k_attn's start (w=0) is L2-warm.
// Dynamic smem: ws[512] | buf0[WT*512] | buf1[WT*512]   (67584 B)
// ---------------------------------------------------------------------------
__global__ __launch_bounds__(512, 2) void k_t(const float* __restrict__ x,
                                              const float* __restrict__ wvec) {
    extern __shared__ float sm[];
    float* ws   = sm;                        // 512
    float* buf0 = sm + F_;
    float* buf1 = buf0 + WT * F_;
    float* bufs[2] = { buf0, buf1 };

    const int b = blockIdx.x, tid = threadIdx.x;
    const float4* xb4 = (const float4*)(x + (size_t)b * W_ * F_);

    ws[tid] = wvec[tid];
    issue_tile(bufs[0], xb4, (NT - 1) * WT, tid);   // preload last tile
    __syncthreads();                                // ws visible

    float acc = 0.f;
    for (int i = 0; i < NT; i++) {
        const int t = NT - 1 - i;            // descending
        const int cur = i & 1, nxt = cur ^ 1;
        if (i < NT - 1) {
            issue_tile(bufs[nxt], xb4, (t - 1) * WT, tid);
            cp_wait<1>();                    // current tile's group done
        } else {
            cp_wait<0>();
        }
        __syncthreads();                     // tile cur ready for all

        const float* xt = bufs[cur];
        const float* wst = ws + t * WT;
        #pragma unroll
        for (int w = 0; w < WT; w++)
            acc += wst[w] * xt[w * F_ + tid];
        __syncthreads();                     // done reading cur before it is re-issued
    }
    g_t[b * F_ + tid] = acc;
}

// ---------------------------------------------------------------------------
// 32x32 tiled SGEMM, BK=32, 256 threads, 2x2 micro with LDS.64.
// C = A[M,Kk] @ (TRANS_B ? Bm[Nn,Kk]^T : Bm[Kk,Nn]) * scale
// ---------------------------------------------------------------------------
template <int TRANS_B>
__global__ __launch_bounds__(256) void gemm32(const float* __restrict__ A,
                                              const float* __restrict__ Bm,
                                              float* __restrict__ C,
                                              int M, int Nn, int Kk, float scale) {
    __shared__ float As[32][36];
    __shared__ float Bs[32][36];
    const int tid = threadIdx.x;
    const int tx = tid & 15, ty = tid >> 4;
    const int m0 = blockIdx.y * 32, n0 = blockIdx.x * 32;
    float c00 = 0.f, c01 = 0.f, c10 = 0.f, c11 = 0.f;

    const int lm = tid >> 3, lk4 = tid & 7;

    for (int k0 = 0; k0 < Kk; k0 += 32) {
        {
            float4 v = *(const float4*)&A[(size_t)(m0 + lm) * Kk + k0 + lk4 * 4];
            As[lk4 * 4 + 0][lm] = v.x;
            As[lk4 * 4 + 1][lm] = v.y;
            As[lk4 * 4 + 2][lm] = v.z;
            As[lk4 * 4 + 3][lm] = v.w;
        }
        if (TRANS_B) {
            float4 v = *(const float4*)&Bm[(size_t)(n0 + lm) * Kk + k0 + lk4 * 4];
            Bs[lk4 * 4 + 0][lm] = v.x;
            Bs[lk4 * 4 + 1][lm] = v.y;
            Bs[lk4 * 4 + 2][lm] = v.z;
            Bs[lk4 * 4 + 3][lm] = v.w;
        } else {
            float4 v = *(const float4*)&Bm[(size_t)(k0 + lm) * Nn + n0 + lk4 * 4];
            Bs[lm][lk4 * 4 + 0] = v.x;
            Bs[lm][lk4 * 4 + 1] = v.y;
            Bs[lm][lk4 * 4 + 2] = v.z;
            Bs[lm][lk4 * 4 + 3] = v.w;
        }
        __syncthreads();
        #pragma unroll
        for (int k = 0; k < 32; k++) {
            const float2 a = *(const float2*)&As[k][ty * 2];
            const float2 b = *(const float2*)&Bs[k][tx * 2];
            c00 += a.x * b.x; c01 += a.x * b.y;
            c10 += a.y * b.x; c11 += a.y * b.y;
        }
        __syncthreads();
    }
    float* Cp = C + (size_t)(m0 + ty * 2) * Nn + n0 + tx * 2;
    Cp[0] = c00 * scale;  Cp[1] = c01 * scale;
    Cp[Nn] = c10 * scale; Cp[Nn + 1] = c11 * scale;
}

// ---------------------------------------------------------------------------
// Pass B: scores + online softmax + weighted accumulate. EXACT R6 structure
// (empirically 51.8us): 2-buffer, issue -> wait<1> -> compute, scalar LDS dot,
// softmax weights computed once by 16 threads.
// Dynamic smem: qks[512] | buf0[WT*512] | buf1[WT*512]   (67584 B)
// ---------------------------------------------------------------------------
__global__ __launch_bounds__(512, 2) void k_attn(const float* __restrict__ x) {
    extern __shared__ float sm[];
    float* qks  = sm;                  // 512
    float* buf0 = sm + F_;             // WT*512
    float* buf1 = buf0 + WT * F_;      // WT*512
    __shared__ float sc[WT];
    __shared__ float ps[WT];

    const int b = blockIdx.x, tid = threadIdx.x;
    const int wi = tid >> 5, lane = tid & 31;

    qks[tid] = g_qk[b * F_ + tid];
    const float4* xb4 = (const float4*)(x + (size_t)b * W_ * F_);

    // Preload tile 0
    issue_tile(buf0, xb4, 0, tid);
    __syncthreads();                         // qks visible

    float qkr[16];
    #pragma unroll
    for (int j = 0; j < 16; j++) qkr[j] = qks[lane + 32 * j];

    float* bufs[2] = { buf0, buf1 };
    float m = -1e30f, s = 0.f, y = 0.f;

    for (int t = 0; t < NT; t++) {
        const int cur = t & 1, nxt = cur ^ 1;
        if (t < NT - 1) {
            issue_tile(bufs[nxt], xb4, (t + 1) * WT, tid);
            cp_wait<1>();
        } else {
            cp_wait<0>();
        }
        __syncthreads();                     // tile cur ready (also guards sc reuse)

        // Each warp: one word's dot product (qk already carries rsqrt(N))
        float d = 0.f;
        const float* xw = &bufs[cur][wi * F_];
        #pragma unroll
        for (int j = 0; j < 16; j++) d += xw[lane + 32 * j] * qkr[j];
        #pragma unroll
        for (int o = 16; o > 0; o >>= 1) d += __shfl_xor_sync(0xffffffffu, d, o);
        if (lane == 0) sc[wi] = d;
        __syncthreads();                     // sc ready

        // mn/corr uniform across threads; p[w] computed once
        float mn = m;
        #pragma unroll
        for (int w = 0; w < WT; w++) mn = fmaxf(mn, sc[w]);
        const float corr = __expf(m - mn);
        if (tid < WT) ps[tid] = __expf(sc[tid] - mn);
        m = mn;
        __syncthreads();                     // ps ready

        // Accumulate (thread owns f = tid)
        float pr[WT];
        #pragma unroll
        for (int w = 0; w < WT; w++) pr[w] = ps[w];
        float psum = 0.f;
        #pragma unroll
        for (int w = 0; w < WT; w++) psum += pr[w];
        s = s * corr + psum;
        y *= corr;
        #pragma unroll
        for (int w = 0; w < WT; w++) y += pr[w] * bufs[cur][w * F_ + tid];
        // no tail barrier: next iter writes bufs[nxt] (disjoint) and sc/ps
        // writes are fenced by the next iteration's barriers.
    }
    g_y[b * F_ + tid] = y / s;
}

// ---------------------------------------------------------------------------
extern "C" void kernel_launch(void* const* d_in, const int* in_sizes, int n_in,
                              void* d_out, int out_size) {
    const float* x    = (const float*)d_in[0];
    const float* wk   = (const float*)d_in[1];
    const float* wq   = (const float*)d_in[2];
    const float* wv   = (const float*)d_in[3];
    const float* wvec = (const float*)d_in[4];
    float* out = (float*)d_out;

    float *pt, *pq, *pqk, *py;
    cudaGetSymbolAddress((void**)&pt,  g_t);
    cudaGetSymbolAddress((void**)&pq,  g_q);
    cudaGetSymbolAddress((void**)&pqk, g_qk);
    cudaGetSymbolAddress((void**)&py,  g_y);

    const int pipe_smem = (F_ + 2 * WT * F_) * sizeof(float);   // 67584
    cudaFuncSetAttribute(k_t,    cudaFuncAttributeMaxDynamicSharedMemorySize, pipe_smem);
    cudaFuncSetAttribute(k_attn, cudaFuncAttributeMaxDynamicSharedMemorySize, pipe_smem);

    const float rsqrtN = 0.04419417382415922f;  // 1/sqrt(512)

    // Pass A over x: t
    k_t<<<B_, 512, pipe_smem>>>(x, wvec);
    // Q = t @ wq                 (256x512x512)
    gemm32<0><<<dim3(N_ / 32, B_ / 32), 256>>>(pt, wq, pq, B_, N_, F_, 1.f);
    // qk = (Q @ wk^T) * rsqrtN   (256x512x512)
    gemm32<1><<<dim3(F_ / 32, B_ / 32), 256>>>(pq, wk, pqk, B_, F_, N_, rsqrtN);
    // Pass B over x: attention
    k_attn<<<B_, 512, pipe_smem>>>(x);
    // out = y @ wv               (256x512x512)
    gemm32<0><<<dim3(N_ / 32, B_ / 32), 256>>>(py, wv, out, B_, N_, F_, 1.f);
}